// round 1
// baseline (speedup 1.0000x reference)
#include <cuda_runtime.h>
#include <math.h>

#define NN 50000
#define NE 1600000
#define FIN 256
#define NF1 200   // H1*F1
#define H1 2
#define F1 100
#define NF2 32    // H2*C
#define H2 1
#define F2 32
#define NEG_SLOPE 0.2f

// ---------------- static scratch (no allocations allowed) ----------------
__device__ float g_z1[(size_t)NN * NF1];
__device__ float g_h1[(size_t)NN * NF1];
__device__ float g_z2[(size_t)NN * NF2];
__device__ float g_el1[NN * H1];
__device__ float g_er1[NN * H1];
__device__ float g_el2[NN * H2];
__device__ float g_er2[NN * H2];
__device__ int   g_deg[NN];
__device__ int   g_row[NN + 1];
__device__ int   g_cur[NN];
__device__ int   g_csr_src[NE];

// ---------------- CSR build ----------------
__global__ void k_zero_deg() {
    int i = blockIdx.x * blockDim.x + threadIdx.x;
    if (i < NN) g_deg[i] = 0;
}

__global__ void k_count(const int* __restrict__ dst) {
    int i = blockIdx.x * blockDim.x + threadIdx.x;
    if (i < NE) atomicAdd(&g_deg[dst[i]], 1);
}

__global__ void k_scan() {
    __shared__ int sh[1024];
    int tid = threadIdx.x;
    const int CH = (NN + 1023) / 1024;
    int base = tid * CH;
    int s = 0;
    for (int i = 0; i < CH; i++) {
        int idx = base + i;
        if (idx < NN) s += g_deg[idx];
    }
    sh[tid] = s;
    __syncthreads();
    for (int off = 1; off < 1024; off <<= 1) {
        int v = (tid >= off) ? sh[tid - off] : 0;
        __syncthreads();
        sh[tid] += v;
        __syncthreads();
    }
    int run = sh[tid] - s;  // exclusive prefix
    for (int i = 0; i < CH; i++) {
        int idx = base + i;
        if (idx < NN) {
            g_row[idx] = run;
            g_cur[idx] = run;
            run += g_deg[idx];
        }
    }
    if (tid == 1023) g_row[NN] = sh[1023];
}

__global__ void k_scatter(const int* __restrict__ src, const int* __restrict__ dst) {
    int i = blockIdx.x * blockDim.x + threadIdx.x;
    if (i < NE) {
        int p = atomicAdd(&g_cur[dst[i]], 1);
        g_csr_src[p] = src[i];
    }
}

// ---------------- GEMM: C[M,N] = A[M,K] @ B[K,N] ----------------
#define TM 64
#define TN 64
#define TKK 16

__global__ __launch_bounds__(256)
void k_gemm(const float* __restrict__ A, const float* __restrict__ B,
            float* __restrict__ C, int M, int N, int K) {
    __shared__ float As[TM][TKK];
    __shared__ float Bs[TKK][TN];
    int tx = threadIdx.x % 16;
    int ty = threadIdx.x / 16;
    int row0 = blockIdx.y * TM;
    int col0 = blockIdx.x * TN;

    float acc[4][4];
#pragma unroll
    for (int i = 0; i < 4; i++)
#pragma unroll
        for (int j = 0; j < 4; j++) acc[i][j] = 0.f;

    for (int k0 = 0; k0 < K; k0 += TKK) {
        // load A tile (coalesced: 16 k per row)
        for (int t = threadIdx.x; t < TM * TKK; t += 256) {
            int r = t / TKK, kk = t % TKK;
            float v = 0.f;
            int gr = row0 + r, gk = k0 + kk;
            if (gr < M && gk < K) v = A[(size_t)gr * K + gk];
            As[r][kk] = v;
        }
        // load B tile
        for (int t = threadIdx.x; t < TKK * TN; t += 256) {
            int kk = t / TN, c = t % TN;
            float v = 0.f;
            int gk = k0 + kk, gc = col0 + c;
            if (gk < K && gc < N) v = B[(size_t)gk * N + gc];
            Bs[kk][c] = v;
        }
        __syncthreads();
#pragma unroll
        for (int kk = 0; kk < TKK; kk++) {
            float a[4], b[4];
#pragma unroll
            for (int i = 0; i < 4; i++) a[i] = As[ty + 16 * i][kk];
#pragma unroll
            for (int j = 0; j < 4; j++) b[j] = Bs[kk][tx + 16 * j];
#pragma unroll
            for (int i = 0; i < 4; i++)
#pragma unroll
                for (int j = 0; j < 4; j++) acc[i][j] = fmaf(a[i], b[j], acc[i][j]);
        }
        __syncthreads();
    }
#pragma unroll
    for (int i = 0; i < 4; i++)
#pragma unroll
        for (int j = 0; j < 4; j++) {
            int r = row0 + ty + 16 * i, c = col0 + tx + 16 * j;
            if (r < M && c < N) C[(size_t)r * N + c] = acc[i][j];
        }
}

// ---------------- attention coefficients: el/er per (node, head) ----------------
template <int H, int F>
__global__ __launch_bounds__(256)
void k_attn(const float* __restrict__ z, const float* __restrict__ al,
            const float* __restrict__ ar, float* __restrict__ el,
            float* __restrict__ er) {
    int warp = (blockIdx.x * blockDim.x + threadIdx.x) >> 5;
    int lane = threadIdx.x & 31;
    if (warp >= NN) return;
    const float* zp = z + (size_t)warp * H * F;
#pragma unroll
    for (int h = 0; h < H; h++) {
        float sl = 0.f, sr = 0.f;
        for (int f = lane; f < F; f += 32) {
            float zv = zp[h * F + f];
            sl += zv * al[h * F + f];
            sr += zv * ar[h * F + f];
        }
#pragma unroll
        for (int o = 16; o; o >>= 1) {
            sl += __shfl_xor_sync(0xffffffffu, sl, o);
            sr += __shfl_xor_sync(0xffffffffu, sr, o);
        }
        if (lane == 0) {
            el[warp * H + h] = sl;
            er[warp * H + h] = sr;
        }
    }
}

__device__ __forceinline__ float lrelu(float x) {
    return x > 0.f ? x : NEG_SLOPE * x;
}

// ---------------- fused edge-softmax + aggregation (warp per dst) ----------------
template <int H, int F, bool ELU>
__global__ __launch_bounds__(256)
void k_agg(const float* __restrict__ z, const float* __restrict__ el,
           const float* __restrict__ er, const float* __restrict__ bias,
           float* __restrict__ out) {
    constexpr int NFv = H * F;
    constexpr int NI = (NFv + 31) / 32;
    int node = (blockIdx.x * blockDim.x + threadIdx.x) >> 5;
    int lane = threadIdx.x & 31;
    if (node >= NN) return;

    int beg = g_row[node];
    int end = g_row[node + 1];

    float erv[H];
#pragma unroll
    for (int h = 0; h < H; h++) erv[h] = er[node * H + h];

    // pass 1: per-head max over incoming edges (lanes stride edges)
    float m[H];
#pragma unroll
    for (int h = 0; h < H; h++) m[h] = -INFINITY;
    for (int e = beg + lane; e < end; e += 32) {
        int s = g_csr_src[e];
        float elv[H];
        if (H == 2) {
            float2 t = ((const float2*)el)[s];
            elv[0] = t.x; elv[1] = t.y;
        } else {
#pragma unroll
            for (int h = 0; h < H; h++) elv[h] = el[s * H + h];
        }
#pragma unroll
        for (int h = 0; h < H; h++) m[h] = fmaxf(m[h], lrelu(elv[h] + erv[h]));
    }
#pragma unroll
    for (int o = 16; o; o >>= 1)
#pragma unroll
        for (int h = 0; h < H; h++)
            m[h] = fmaxf(m[h], __shfl_xor_sync(0xffffffffu, m[h], o));

    // pass 2: acc = sum a_i * z[src_i],  denom = sum a_i
    float acc[NI];
#pragma unroll
    for (int i = 0; i < NI; i++) acc[i] = 0.f;
    float denom[H];
#pragma unroll
    for (int h = 0; h < H; h++) denom[h] = 0.f;

    for (int base = beg; base < end; base += 32) {
        int e = base + lane;
        int s = 0;
        float a[H];
#pragma unroll
        for (int h = 0; h < H; h++) a[h] = 0.f;
        if (e < end) {
            s = g_csr_src[e];
            float elv[H];
            if (H == 2) {
                float2 t = ((const float2*)el)[s];
                elv[0] = t.x; elv[1] = t.y;
            } else {
#pragma unroll
                for (int h = 0; h < H; h++) elv[h] = el[s * H + h];
            }
#pragma unroll
            for (int h = 0; h < H; h++) {
                float x = lrelu(elv[h] + erv[h]);
                a[h] = __expf(x - m[h]);
                denom[h] += a[h];
            }
        }
        int cnt = min(32, end - base);
        for (int j = 0; j < cnt; j++) {
            int sj = __shfl_sync(0xffffffffu, s, j);
            float aj[H];
#pragma unroll
            for (int h = 0; h < H; h++) aj[h] = __shfl_sync(0xffffffffu, a[h], j);
            const float* zp = z + (size_t)sj * NFv;
#pragma unroll
            for (int i = 0; i < NI; i++) {
                int f = lane + 32 * i;
                if (f < NFv) {
                    int h = f / F;
                    acc[i] = fmaf(zp[f], aj[h], acc[i]);
                }
            }
        }
    }
#pragma unroll
    for (int o = 16; o; o >>= 1)
#pragma unroll
        for (int h = 0; h < H; h++)
            denom[h] += __shfl_xor_sync(0xffffffffu, denom[h], o);

    float inv[H];
#pragma unroll
    for (int h = 0; h < H; h++) inv[h] = (denom[h] > 0.f) ? 1.f / denom[h] : 0.f;

#pragma unroll
    for (int i = 0; i < NI; i++) {
        int f = lane + 32 * i;
        if (f < NFv) {
            int h = f / F;
            float v = acc[i] * inv[h] + bias[f];
            if (ELU) v = v > 0.f ? v : expm1f(v);
            out[(size_t)node * NFv + f] = v;
        }
    }
}

// ---------------- host launch ----------------
extern "C" void kernel_launch(void* const* d_in, const int* in_sizes, int n_in,
                              void* d_out, int out_size) {
    const float* features = (const float*)d_in[0];
    const float* W1  = (const float*)d_in[1];
    const float* al1 = (const float*)d_in[2];
    const float* ar1 = (const float*)d_in[3];
    const float* b1  = (const float*)d_in[4];
    const float* W2  = (const float*)d_in[5];
    const float* al2 = (const float*)d_in[6];
    const float* ar2 = (const float*)d_in[7];
    const float* b2  = (const float*)d_in[8];
    const int*   src = (const int*)d_in[9];
    const int*   dst = (const int*)d_in[10];
    float* out = (float*)d_out;

    void *p_z1, *p_h1, *p_z2, *p_el1, *p_er1, *p_el2, *p_er2;
    cudaGetSymbolAddress(&p_z1, g_z1);
    cudaGetSymbolAddress(&p_h1, g_h1);
    cudaGetSymbolAddress(&p_z2, g_z2);
    cudaGetSymbolAddress(&p_el1, g_el1);
    cudaGetSymbolAddress(&p_er1, g_er1);
    cudaGetSymbolAddress(&p_el2, g_el2);
    cudaGetSymbolAddress(&p_er2, g_er2);

    // CSR build (dst-indexed)
    k_zero_deg<<<(NN + 255) / 256, 256>>>();
    k_count<<<(NE + 255) / 256, 256>>>(dst);
    k_scan<<<1, 1024>>>();
    k_scatter<<<(NE + 255) / 256, 256>>>(src, dst);

    // layer 1
    {
        dim3 grid((NF1 + TN - 1) / TN, (NN + TM - 1) / TM);
        k_gemm<<<grid, 256>>>(features, W1, (float*)p_z1, NN, NF1, FIN);
    }
    k_attn<H1, F1><<<(NN * 32 + 255) / 256, 256>>>((const float*)p_z1, al1, ar1,
                                                   (float*)p_el1, (float*)p_er1);
    k_agg<H1, F1, true><<<(NN * 32 + 255) / 256, 256>>>(
        (const float*)p_z1, (const float*)p_el1, (const float*)p_er1, b1,
        (float*)p_h1);

    // layer 2
    {
        dim3 grid((NF2 + TN - 1) / TN, (NN + TM - 1) / TM);
        k_gemm<<<grid, 256>>>((const float*)p_h1, W2, (float*)p_z2, NN, NF2, NF1);
    }
    k_attn<H2, F2><<<(NN * 32 + 255) / 256, 256>>>((const float*)p_z2, al2, ar2,
                                                   (float*)p_el2, (float*)p_er2);
    k_agg<H2, F2, false><<<(NN * 32 + 255) / 256, 256>>>(
        (const float*)p_z2, (const float*)p_el2, (const float*)p_er2, b2, out);
}

// round 12
// speedup vs baseline: 1.4317x; 1.4317x over previous
#include <cuda_runtime.h>
#include <math.h>

#define NN 50000
#define NE 1600000
#define FIN 256
#define NF1 200   // H1*F1
#define H1 2
#define F1 100
#define NF2 32
#define NEG_SLOPE 0.2f

// ---------------- static scratch ----------------
__device__ float g_z1[(size_t)NN * NF1];
__device__ float g_h1[(size_t)NN * NF1];
__device__ float g_z2[(size_t)NN * NF2];
__device__ float g_el1[NN * H1];
__device__ float g_er1[NN * H1];
__device__ float g_el2[NN];
__device__ float g_er2[NN];
__device__ int   g_deg[NN];
__device__ int   g_row[NN + 1];
__device__ int   g_cur[NN];
__device__ int   g_csr_src[NE];

// ---------------- CSR build ----------------
__global__ void k_zero_deg() {
    int i = blockIdx.x * blockDim.x + threadIdx.x;
    if (i < NN) g_deg[i] = 0;
}

__global__ void k_count(const int* __restrict__ dst) {
    int i = blockIdx.x * blockDim.x + threadIdx.x;
    if (i < NE) atomicAdd(&g_deg[dst[i]], 1);
}

__global__ void k_scan() {
    __shared__ int sh[1024];
    int tid = threadIdx.x;
    const int CH = (NN + 1023) / 1024;
    int base = tid * CH;
    int s = 0;
    for (int i = 0; i < CH; i++) {
        int idx = base + i;
        if (idx < NN) s += g_deg[idx];
    }
    sh[tid] = s;
    __syncthreads();
    for (int off = 1; off < 1024; off <<= 1) {
        int v = (tid >= off) ? sh[tid - off] : 0;
        __syncthreads();
        sh[tid] += v;
        __syncthreads();
    }
    int run = sh[tid] - s;
    for (int i = 0; i < CH; i++) {
        int idx = base + i;
        if (idx < NN) {
            g_row[idx] = run;
            g_cur[idx] = run;
            run += g_deg[idx];
        }
    }
    if (tid == 1023) g_row[NN] = sh[1023];
}

__global__ void k_scatter(const int* __restrict__ src, const int* __restrict__ dst) {
    int i = blockIdx.x * blockDim.x + threadIdx.x;
    if (i < NE) {
        int p = atomicAdd(&g_cur[dst[i]], 1);
        g_csr_src[p] = src[i];
    }
}

// ---------------- 3xTF32 tensor-core GEMM ----------------
// C[M,N] = A[M,K] @ B[K,N]; requires K,N multiples of 4.
__device__ __forceinline__ void split_tf32(float x, unsigned& hi, unsigned& lo) {
    asm("cvt.rna.tf32.f32 %0, %1;" : "=r"(hi) : "f"(x));
    float l = x - __uint_as_float(hi);
    asm("cvt.rna.tf32.f32 %0, %1;" : "=r"(lo) : "f"(l));
}

#define MMA_TF32(d, a, b)                                                 \
    asm volatile(                                                         \
        "mma.sync.aligned.m16n8k8.row.col.f32.tf32.tf32.f32 "             \
        "{%0,%1,%2,%3}, {%4,%5,%6,%7}, {%8,%9}, {%0,%1,%2,%3};"           \
        : "+f"(d[0]), "+f"(d[1]), "+f"(d[2]), "+f"(d[3])                  \
        : "r"(a[0]), "r"(a[1]), "r"(a[2]), "r"(a[3]), "r"(b[0]), "r"(b[1]))

__global__ __launch_bounds__(256)
void k_gemm_tf32(const float* __restrict__ A, const float* __restrict__ B,
                 float* __restrict__ C, int M, int N, int K) {
    __shared__ float As[128][36];  // [m][k], stride 36: conflict-free frag loads
    __shared__ float Bs[32][72];   // [k][n], stride 72: conflict-free frag loads
    int tid = threadIdx.x;
    int wid = tid >> 5, lane = tid & 31;
    int gid = lane >> 2, tig = lane & 3;
    int wm = wid & 3, wn = wid >> 2;  // 4x2 warp grid: 32 rows x 32 cols each
    int r0 = blockIdx.y * 128, c0 = blockIdx.x * 64;

    float acc[2][4][4];
#pragma unroll
    for (int mt = 0; mt < 2; mt++)
#pragma unroll
        for (int nt = 0; nt < 4; nt++)
#pragma unroll
            for (int i = 0; i < 4; i++) acc[mt][nt][i] = 0.f;

    for (int k0 = 0; k0 < K; k0 += 32) {
        // load A tile: 128x32, thread -> row tid/8, k-group tid%8 (float4)
        {
            int rr = tid >> 3, kg = (tid & 7) << 2;
#pragma unroll
            for (int i = 0; i < 4; i++) {
                int r = rr + (i << 5);
                int gr = r0 + r, gk = k0 + kg;
                float4 v = make_float4(0.f, 0.f, 0.f, 0.f);
                if (gr < M && gk < K)  // K multiple of 4 -> full vec in range
                    v = *reinterpret_cast<const float4*>(&A[(size_t)gr * K + gk]);
                *reinterpret_cast<float4*>(&As[r][kg]) = v;
            }
        }
        // load B tile: 32x64, thread -> row tid/16, col-group tid%16 (float4)
        {
            int kr = tid >> 4, cg = (tid & 15) << 2;
#pragma unroll
            for (int i = 0; i < 2; i++) {
                int k = kr + (i << 4);
                int gk = k0 + k, gc = c0 + cg;
                float4 v = make_float4(0.f, 0.f, 0.f, 0.f);
                if (gk < K && gc < N)  // N multiple of 4
                    v = *reinterpret_cast<const float4*>(&B[(size_t)gk * N + gc]);
                *reinterpret_cast<float4*>(&Bs[k][cg]) = v;
            }
        }
        __syncthreads();
#pragma unroll
        for (int ks = 0; ks < 4; ks++) {
            int kb = (ks << 3) + tig;
            unsigned ah[2][4], alo[2][4];
#pragma unroll
            for (int mt = 0; mt < 2; mt++) {
                int mb = wm * 32 + mt * 16 + gid;
                float a0 = As[mb][kb];
                float a1 = As[mb + 8][kb];
                float a2 = As[mb][kb + 4];
                float a3 = As[mb + 8][kb + 4];
                split_tf32(a0, ah[mt][0], alo[mt][0]);
                split_tf32(a1, ah[mt][1], alo[mt][1]);
                split_tf32(a2, ah[mt][2], alo[mt][2]);
                split_tf32(a3, ah[mt][3], alo[mt][3]);
            }
            unsigned bh[4][2], bl[4][2];
#pragma unroll
            for (int nt = 0; nt < 4; nt++) {
                int nb = wn * 32 + nt * 8 + gid;
                float b0 = Bs[kb][nb];
                float b1 = Bs[kb + 4][nb];
                split_tf32(b0, bh[nt][0], bl[nt][0]);
                split_tf32(b1, bh[nt][1], bl[nt][1]);
            }
#pragma unroll
            for (int mt = 0; mt < 2; mt++)
#pragma unroll
                for (int nt = 0; nt < 4; nt++) {
                    MMA_TF32(acc[mt][nt], ah[mt], bh[nt]);
                    MMA_TF32(acc[mt][nt], ah[mt], bl[nt]);
                    MMA_TF32(acc[mt][nt], alo[mt], bh[nt]);
                }
        }
        __syncthreads();
    }

#pragma unroll
    for (int mt = 0; mt < 2; mt++)
#pragma unroll
        for (int nt = 0; nt < 4; nt++) {
            int row = r0 + wm * 32 + mt * 16 + gid;
            int col = c0 + wn * 32 + nt * 8 + (tig << 1);
            if (col < N) {  // col even, N even -> col+1 also < N
                if (row < M) {
                    float2 v = make_float2(acc[mt][nt][0], acc[mt][nt][1]);
                    *reinterpret_cast<float2*>(&C[(size_t)row * N + col]) = v;
                }
                if (row + 8 < M) {
                    float2 v = make_float2(acc[mt][nt][2], acc[mt][nt][3]);
                    *reinterpret_cast<float2*>(&C[(size_t)(row + 8) * N + col]) = v;
                }
            }
        }
}

// ---------------- attention coefficients ----------------
__global__ __launch_bounds__(256)
void k_attn200(const float* __restrict__ z, const float* __restrict__ al,
               const float* __restrict__ ar, float* __restrict__ el,
               float* __restrict__ er) {
    int node = (blockIdx.x * blockDim.x + threadIdx.x) >> 5;
    int lane = threadIdx.x & 31;
    if (node >= NN) return;
    const float4* zp = reinterpret_cast<const float4*>(z) + (size_t)node * 50;
    const float4* al4 = reinterpret_cast<const float4*>(al);
    const float4* ar4 = reinterpret_cast<const float4*>(ar);
    float sl0 = 0.f, sl1 = 0.f, sr0 = 0.f, sr1 = 0.f;
    {
        float4 v = zp[lane], a = al4[lane], r = ar4[lane];
        float dl = v.x * a.x + v.y * a.y + v.z * a.z + v.w * a.w;
        float dr = v.x * r.x + v.y * r.y + v.z * r.z + v.w * r.w;
        if (lane < 25) { sl0 = dl; sr0 = dr; } else { sl1 = dl; sr1 = dr; }
    }
    if (lane < 18) {
        float4 v = zp[32 + lane], a = al4[32 + lane], r = ar4[32 + lane];
        sl1 += v.x * a.x + v.y * a.y + v.z * a.z + v.w * a.w;
        sr1 += v.x * r.x + v.y * r.y + v.z * r.z + v.w * r.w;
    }
#pragma unroll
    for (int o = 16; o; o >>= 1) {
        sl0 += __shfl_xor_sync(0xffffffffu, sl0, o);
        sl1 += __shfl_xor_sync(0xffffffffu, sl1, o);
        sr0 += __shfl_xor_sync(0xffffffffu, sr0, o);
        sr1 += __shfl_xor_sync(0xffffffffu, sr1, o);
    }
    if (lane == 0) {
        el[node * 2] = sl0; el[node * 2 + 1] = sl1;
        er[node * 2] = sr0; er[node * 2 + 1] = sr1;
    }
}

__global__ __launch_bounds__(256)
void k_attn32(const float* __restrict__ z, const float* __restrict__ al,
              const float* __restrict__ ar, float* __restrict__ el,
              float* __restrict__ er) {
    int node = (blockIdx.x * blockDim.x + threadIdx.x) >> 5;
    int lane = threadIdx.x & 31;
    if (node >= NN) return;
    float zv = z[(size_t)node * 32 + lane];
    float sl = zv * al[lane];
    float sr = zv * ar[lane];
#pragma unroll
    for (int o = 16; o; o >>= 1) {
        sl += __shfl_xor_sync(0xffffffffu, sl, o);
        sr += __shfl_xor_sync(0xffffffffu, sr, o);
    }
    if (lane == 0) { el[node] = sl; er[node] = sr; }
}

__device__ __forceinline__ float lrelu(float x) {
    return x > 0.f ? x : NEG_SLOPE * x;
}

// ---------------- fused softmax+agg, layer1 (H=2, 200 feats, ELU) ----------------
__global__ __launch_bounds__(256)
void k_agg200(const float* __restrict__ z, const float* __restrict__ el,
              const float* __restrict__ er, const float* __restrict__ bias,
              float* __restrict__ out) {
    int node = (blockIdx.x * blockDim.x + threadIdx.x) >> 5;
    int lane = threadIdx.x & 31;
    if (node >= NN) return;
    int beg = g_row[node], end = g_row[node + 1];

    float2 erv = reinterpret_cast<const float2*>(er)[node];
    float4 acc0 = make_float4(0.f, 0.f, 0.f, 0.f);
    float4 acc1 = make_float4(0.f, 0.f, 0.f, 0.f);
    float den0 = 0.f, den1 = 0.f;

    for (int base = beg; base < end; base += 32) {
        int e = base + lane;
        int s = 0;
        float a0 = 0.f, a1 = 0.f;
        if (e < end) {
            s = g_csr_src[e];
            float2 t = reinterpret_cast<const float2*>(el)[s];
            a0 = __expf(lrelu(t.x + erv.x));
            a1 = __expf(lrelu(t.y + erv.y));
            den0 += a0; den1 += a1;
        }
        int cnt = min(32, end - base);
        for (int j = 0; j < cnt; j++) {
            int sj = __shfl_sync(0xffffffffu, s, j);
            float w0 = __shfl_sync(0xffffffffu, a0, j);
            float w1 = __shfl_sync(0xffffffffu, a1, j);
            const float4* zp = reinterpret_cast<const float4*>(z) + (size_t)sj * 50;
            float4 v = zp[lane];
            float w = (lane < 25) ? w0 : w1;  // f4 idx < 25 -> head 0
            acc0.x = fmaf(v.x, w, acc0.x);
            acc0.y = fmaf(v.y, w, acc0.y);
            acc0.z = fmaf(v.z, w, acc0.z);
            acc0.w = fmaf(v.w, w, acc0.w);
            if (lane < 18) {
                float4 v2 = zp[32 + lane];  // idx 32..49 -> head 1
                acc1.x = fmaf(v2.x, w1, acc1.x);
                acc1.y = fmaf(v2.y, w1, acc1.y);
                acc1.z = fmaf(v2.z, w1, acc1.z);
                acc1.w = fmaf(v2.w, w1, acc1.w);
            }
        }
    }
#pragma unroll
    for (int o = 16; o; o >>= 1) {
        den0 += __shfl_xor_sync(0xffffffffu, den0, o);
        den1 += __shfl_xor_sync(0xffffffffu, den1, o);
    }
    float inv0 = (den0 > 0.f) ? 1.f / den0 : 0.f;
    float inv1 = (den1 > 0.f) ? 1.f / den1 : 0.f;

    const float4* b4 = reinterpret_cast<const float4*>(bias);
    float4* o4 = reinterpret_cast<float4*>(out) + (size_t)node * 50;
    {
        float w = (lane < 25) ? inv0 : inv1;
        float4 b = b4[lane];
        float4 v;
        v.x = acc0.x * w + b.x; v.y = acc0.y * w + b.y;
        v.z = acc0.z * w + b.z; v.w = acc0.w * w + b.w;
        v.x = v.x > 0.f ? v.x : expm1f(v.x);
        v.y = v.y > 0.f ? v.y : expm1f(v.y);
        v.z = v.z > 0.f ? v.z : expm1f(v.z);
        v.w = v.w > 0.f ? v.w : expm1f(v.w);
        o4[lane] = v;
    }
    if (lane < 18) {
        float4 b = b4[32 + lane];
        float4 v;
        v.x = acc1.x * inv1 + b.x; v.y = acc1.y * inv1 + b.y;
        v.z = acc1.z * inv1 + b.z; v.w = acc1.w * inv1 + b.w;
        v.x = v.x > 0.f ? v.x : expm1f(v.x);
        v.y = v.y > 0.f ? v.y : expm1f(v.y);
        v.z = v.z > 0.f ? v.z : expm1f(v.z);
        v.w = v.w > 0.f ? v.w : expm1f(v.w);
        o4[32 + lane] = v;
    }
}

// ---------------- fused softmax+agg, layer2 (H=1, 32 feats) ----------------
__global__ __launch_bounds__(256)
void k_agg32(const float* __restrict__ z, const float* __restrict__ el,
             const float* __restrict__ er, const float* __restrict__ bias,
             float* __restrict__ out) {
    int node = (blockIdx.x * blockDim.x + threadIdx.x) >> 5;
    int lane = threadIdx.x & 31;
    if (node >= NN) return;
    int beg = g_row[node], end = g_row[node + 1];

    float erv = er[node];
    float acc = 0.f, den = 0.f;

    for (int base = beg; base < end; base += 32) {
        int e = base + lane;
        int s = 0;
        float a = 0.f;
        if (e < end) {
            s = g_csr_src[e];
            a = __expf(lrelu(el[s] + erv));
            den += a;
        }
        int cnt = min(32, end - base);
        for (int j = 0; j < cnt; j++) {
            int sj = __shfl_sync(0xffffffffu, s, j);
            float aj = __shfl_sync(0xffffffffu, a, j);
            acc = fmaf(z[(size_t)sj * 32 + lane], aj, acc);
        }
    }
#pragma unroll
    for (int o = 16; o; o >>= 1)
        den += __shfl_xor_sync(0xffffffffu, den, o);
    float inv = (den > 0.f) ? 1.f / den : 0.f;
    out[(size_t)node * 32 + lane] = acc * inv + bias[lane];
}

// ---------------- host launch ----------------
extern "C" void kernel_launch(void* const* d_in, const int* in_sizes, int n_in,
                              void* d_out, int out_size) {
    const float* features = (const float*)d_in[0];
    const float* W1  = (const float*)d_in[1];
    const float* al1 = (const float*)d_in[2];
    const float* ar1 = (const float*)d_in[3];
    const float* b1  = (const float*)d_in[4];
    const float* W2  = (const float*)d_in[5];
    const float* al2 = (const float*)d_in[6];
    const float* ar2 = (const float*)d_in[7];
    const float* b2  = (const float*)d_in[8];
    const int*   src = (const int*)d_in[9];
    const int*   dst = (const int*)d_in[10];
    float* out = (float*)d_out;

    void *p_z1, *p_h1, *p_z2, *p_el1, *p_er1, *p_el2, *p_er2;
    cudaGetSymbolAddress(&p_z1, g_z1);
    cudaGetSymbolAddress(&p_h1, g_h1);
    cudaGetSymbolAddress(&p_z2, g_z2);
    cudaGetSymbolAddress(&p_el1, g_el1);
    cudaGetSymbolAddress(&p_er1, g_er1);
    cudaGetSymbolAddress(&p_el2, g_el2);
    cudaGetSymbolAddress(&p_er2, g_er2);

    // CSR build (dst-indexed)
    k_zero_deg<<<(NN + 255) / 256, 256>>>();
    k_count<<<(NE + 255) / 256, 256>>>(dst);
    k_scan<<<1, 1024>>>();
    k_scatter<<<(NE + 255) / 256, 256>>>(src, dst);

    const int warps_grid = (NN * 32 + 255) / 256;

    // layer 1
    {
        dim3 grid((NF1 + 63) / 64, (NN + 127) / 128);
        k_gemm_tf32<<<grid, 256>>>(features, W1, (float*)p_z1, NN, NF1, FIN);
    }
    k_attn200<<<warps_grid, 256>>>((const float*)p_z1, al1, ar1,
                                   (float*)p_el1, (float*)p_er1);
    k_agg200<<<warps_grid, 256>>>((const float*)p_z1, (const float*)p_el1,
                                  (const float*)p_er1, b1, (float*)p_h1);

    // layer 2
    {
        dim3 grid((NF2 + 63) / 64, (NN + 127) / 128);
        k_gemm_tf32<<<grid, 256>>>((const float*)p_h1, W2, (float*)p_z2, NN, NF2, NF1);
    }
    k_attn32<<<warps_grid, 256>>>((const float*)p_z2, al2, ar2,
                                  (float*)p_el2, (float*)p_er2);
    k_agg32<<<warps_grid, 256>>>((const float*)p_z2, (const float*)p_el2,
                                 (const float*)p_er2, b2, out);
}